// round 5
// baseline (speedup 1.0000x reference)
#include <cuda_runtime.h>
#include <math.h>

#define BB  8
#define HH  8
#define SEQ 1024
#define DM  512
#define DEP 64

// ---- scratch (allocation-free: device globals) --------------------------
__device__ float g_Q[BB*HH*SEQ*DEP];   // 16 MB each
__device__ float g_K[BB*HH*SEQ*DEP];
__device__ float g_V[BB*HH*SEQ*DEP];
__device__ float g_X[BB*HH*SEQ*DEP];

// =========================================================================
// Kernel 1: projection GEMM  Out[b,h,s,d] = X[m,:] @ W[:, h*64+d] + bias
// M=8192, N=512, K=512.  64x64 block tile, BK=16, 4x4 microtile, 256 thr.
// =========================================================================
__global__ __launch_bounds__(256)
void proj_kernel(const float* __restrict__ X, const float* __restrict__ W,
                 const float* __restrict__ bias, float* __restrict__ Out)
{
    __shared__ float As[64*17];
    __shared__ float Bs[16*68];

    const int t  = threadIdx.x;
    const int tx = t & 15, ty = t >> 4;
    const int m0 = blockIdx.x * 64;
    const int h  = blockIdx.y;           // BN = 64 == depth -> one head per tile
    const int n0 = h * 64;
    const int ar = t >> 2, ac = (t & 3) * 4;   // A loader: 64 rows x 4 f4
    const int br = t >> 4, bc = (t & 15) * 4;  // B loader: 16 rows x 16 f4

    float acc[4][4] = {};

    for (int kk = 0; kk < DM; kk += 16) {
        float4 av = *(const float4*)&X[(size_t)(m0 + ar) * DM + kk + ac];
        As[ar*17 + ac + 0] = av.x; As[ar*17 + ac + 1] = av.y;
        As[ar*17 + ac + 2] = av.z; As[ar*17 + ac + 3] = av.w;
        float4 bv = *(const float4*)&W[(size_t)(kk + br) * DM + n0 + bc];
        *(float4*)&Bs[br*68 + bc] = bv;
        __syncthreads();
#pragma unroll
        for (int k = 0; k < 16; k++) {
            float a0 = As[(ty*4+0)*17 + k];
            float a1 = As[(ty*4+1)*17 + k];
            float a2 = As[(ty*4+2)*17 + k];
            float a3 = As[(ty*4+3)*17 + k];
            float4 b4 = *(const float4*)&Bs[k*68 + tx*4];
            acc[0][0] = fmaf(a0,b4.x,acc[0][0]); acc[0][1] = fmaf(a0,b4.y,acc[0][1]);
            acc[0][2] = fmaf(a0,b4.z,acc[0][2]); acc[0][3] = fmaf(a0,b4.w,acc[0][3]);
            acc[1][0] = fmaf(a1,b4.x,acc[1][0]); acc[1][1] = fmaf(a1,b4.y,acc[1][1]);
            acc[1][2] = fmaf(a1,b4.z,acc[1][2]); acc[1][3] = fmaf(a1,b4.w,acc[1][3]);
            acc[2][0] = fmaf(a2,b4.x,acc[2][0]); acc[2][1] = fmaf(a2,b4.y,acc[2][1]);
            acc[2][2] = fmaf(a2,b4.z,acc[2][2]); acc[2][3] = fmaf(a2,b4.w,acc[2][3]);
            acc[3][0] = fmaf(a3,b4.x,acc[3][0]); acc[3][1] = fmaf(a3,b4.y,acc[3][1]);
            acc[3][2] = fmaf(a3,b4.z,acc[3][2]); acc[3][3] = fmaf(a3,b4.w,acc[3][3]);
        }
        __syncthreads();
    }

    float4 bias4 = *(const float4*)&bias[n0 + tx*4];
#pragma unroll
    for (int i = 0; i < 4; i++) {
        int m = m0 + ty*4 + i;
        int bbatch = m >> 10, s = m & 1023;
        float4 o = make_float4(acc[i][0] + bias4.x, acc[i][1] + bias4.y,
                               acc[i][2] + bias4.z, acc[i][3] + bias4.w);
        *(float4*)&Out[(((size_t)bbatch*HH + h)*SEQ + s)*DEP + tx*4] = o;
    }
}

// =========================================================================
// Kernel 3: output GEMM  out[m,n] = X[b,h,s,:] @ wo + bo   (gathered A)
// =========================================================================
__global__ __launch_bounds__(256)
void outproj_kernel(const float* __restrict__ W, const float* __restrict__ bias,
                    float* __restrict__ Out)
{
    __shared__ float As[64*17];
    __shared__ float Bs[16*68];

    const int t  = threadIdx.x;
    const int tx = t & 15, ty = t >> 4;
    const int m0 = blockIdx.x * 64;
    const int n0 = blockIdx.y * 64;
    const int ar = t >> 2, ac = (t & 3) * 4;
    const int br = t >> 4, bc = (t & 15) * 4;

    float acc[4][4] = {};

    const int mA = m0 + ar;
    const int bbA = mA >> 10, sA = mA & 1023;

    for (int kk = 0; kk < DM; kk += 16) {
        int kb = kk + ac;                  // multiple of 4, never crosses a head
        int hsrc = kb >> 6, dd = kb & 63;
        float4 av = *(const float4*)&g_X[(((size_t)bbA*HH + hsrc)*SEQ + sA)*DEP + dd];
        As[ar*17 + ac + 0] = av.x; As[ar*17 + ac + 1] = av.y;
        As[ar*17 + ac + 2] = av.z; As[ar*17 + ac + 3] = av.w;
        float4 bv = *(const float4*)&W[(size_t)(kk + br) * DM + n0 + bc];
        *(float4*)&Bs[br*68 + bc] = bv;
        __syncthreads();
#pragma unroll
        for (int k = 0; k < 16; k++) {
            float a0 = As[(ty*4+0)*17 + k];
            float a1 = As[(ty*4+1)*17 + k];
            float a2 = As[(ty*4+2)*17 + k];
            float a3 = As[(ty*4+3)*17 + k];
            float4 b4 = *(const float4*)&Bs[k*68 + tx*4];
            acc[0][0] = fmaf(a0,b4.x,acc[0][0]); acc[0][1] = fmaf(a0,b4.y,acc[0][1]);
            acc[0][2] = fmaf(a0,b4.z,acc[0][2]); acc[0][3] = fmaf(a0,b4.w,acc[0][3]);
            acc[1][0] = fmaf(a1,b4.x,acc[1][0]); acc[1][1] = fmaf(a1,b4.y,acc[1][1]);
            acc[1][2] = fmaf(a1,b4.z,acc[1][2]); acc[1][3] = fmaf(a1,b4.w,acc[1][3]);
            acc[2][0] = fmaf(a2,b4.x,acc[2][0]); acc[2][1] = fmaf(a2,b4.y,acc[2][1]);
            acc[2][2] = fmaf(a2,b4.z,acc[2][2]); acc[2][3] = fmaf(a2,b4.w,acc[2][3]);
            acc[3][0] = fmaf(a3,b4.x,acc[3][0]); acc[3][1] = fmaf(a3,b4.y,acc[3][1]);
            acc[3][2] = fmaf(a3,b4.z,acc[3][2]); acc[3][3] = fmaf(a3,b4.w,acc[3][3]);
        }
        __syncthreads();
    }

    float4 bias4 = *(const float4*)&bias[n0 + tx*4];
#pragma unroll
    for (int i = 0; i < 4; i++) {
        int m = m0 + ty*4 + i;
        float4 o = make_float4(acc[i][0] + bias4.x, acc[i][1] + bias4.y,
                               acc[i][2] + bias4.z, acc[i][3] + bias4.w);
        *(float4*)&Out[(size_t)m*DM + n0 + tx*4] = o;
    }
}

// =========================================================================
// Kernel 2: attention.  One CTA per (b, h, 16-row q-tile).
//   phase 1: S_tile = Q_tile @ K^T * 0.125          (scores in smem)
//   softmax: masked, per-row warp reduction, then * additional_weights,
//            written to attn output region
//   phase 2: X_tile = A_tile @ V  ->  g_X
// =========================================================================
#define SD   65     // K/V smem row pitch
#define SROW 1025   // scores smem row pitch
#define ATTN_SMEM_BYTES ((16*65 + 128*SD + 16*SROW + SEQ) * 4)

__global__ __launch_bounds__(256)
void attn_kernel(const float* __restrict__ mask, const float* __restrict__ aw,
                 float* __restrict__ attn_out)
{
    extern __shared__ float sm[];
    float* Qs = sm;                 // 16 x 65
    float* Ks = Qs + 16*65;         // 128 x SD (K tile, reused for V)
    float* Ss = Ks + 128*SD;        // 16 x SROW
    float* Ms = Ss + 16*SROW;       // 1024

    const int t  = threadIdx.x;
    const int qt = blockIdx.x;           // 0..63
    const int h  = blockIdx.y;
    const int b  = blockIdx.z;
    const int bh = b*HH + h;
    const int q0 = qt*16;

    const float* Qg = g_Q + ((size_t)bh*SEQ + q0)*DEP;
    const float* Kg = g_K + (size_t)bh*SEQ*DEP;
    const float* Vg = g_V + (size_t)bh*SEQ*DEP;

    // load Q tile (16x64) and mask row (1024)
    {
        int r = t >> 4, c = (t & 15) * 4;
        float4 v = *(const float4*)&Qg[r*DEP + c];
        Qs[r*65 + c + 0] = v.x; Qs[r*65 + c + 1] = v.y;
        Qs[r*65 + c + 2] = v.z; Qs[r*65 + c + 3] = v.w;
    }
    for (int i = t; i < SEQ; i += 256) Ms[i] = mask[(size_t)b*SEQ + i];

    const int w = t >> 5, lane = t & 31;   // warp w owns q-rows 2w, 2w+1
    const int qa = 2*w, qb = 2*w + 1;

    // -------- phase 1: scores --------
    for (int kt = 0; kt < 8; kt++) {
        __syncthreads();                    // previous tile fully consumed
#pragma unroll
        for (int it = 0; it < 8; it++) {
            int lin = t + 256*it;           // 0..2047 float4 slots
            int r = lin >> 4, c = (lin & 15) * 4;
            float4 v = *(const float4*)&Kg[(size_t)(kt*128 + r)*DEP + c];
            Ks[r*SD + c + 0] = v.x; Ks[r*SD + c + 1] = v.y;
            Ks[r*SD + c + 2] = v.z; Ks[r*SD + c + 3] = v.w;
        }
        __syncthreads();

        float acc0[4] = {0,0,0,0}, acc1[4] = {0,0,0,0};
#pragma unroll 16
        for (int d = 0; d < DEP; d++) {
            float a0 = Qs[qa*65 + d];       // broadcast within warp
            float a1 = Qs[qb*65 + d];
#pragma unroll
            for (int j = 0; j < 4; j++) {
                float kv = Ks[(lane + 32*j)*SD + d];   // conflict-free (stride 65)
                acc0[j] = fmaf(a0, kv, acc0[j]);
                acc1[j] = fmaf(a1, kv, acc1[j]);
            }
        }
#pragma unroll
        for (int j = 0; j < 4; j++) {
            int k = kt*128 + lane + 32*j;
            Ss[qa*SROW + k] = acc0[j] * 0.125f;
            Ss[qb*SROW + k] = acc1[j] * 0.125f;
        }
    }
    __syncthreads();

    // -------- masked softmax + additional_weights, write attn --------
    // pass 1: apply mask in-place + row max; pass 2: exp + sum;
    // pass 3: normalize * aw, store to smem and gmem.
#pragma unroll
    for (int rr = 0; rr < 2; rr++) {
        int r = 2*w + rr;
        float mx = -3.0e38f;
#pragma unroll
        for (int i = 0; i < 32; i++) {
            int k = lane + 32*i;
            float v = fmaf(Ms[k], -1.0e9f, Ss[r*SROW + k]);
            Ss[r*SROW + k] = v;            // store masked score once
            mx = fmaxf(mx, v);
        }
#pragma unroll
        for (int off = 16; off > 0; off >>= 1)
            mx = fmaxf(mx, __shfl_xor_sync(0xffffffffu, mx, off));
        float sum = 0.f;
#pragma unroll
        for (int i = 0; i < 32; i++) {
            int k = lane + 32*i;
            float v = expf(Ss[r*SROW + k] - mx);
            Ss[r*SROW + k] = v;
            sum += v;
        }
#pragma unroll
        for (int off = 16; off > 0; off >>= 1)
            sum += __shfl_xor_sync(0xffffffffu, sum, off);
        float inv = 1.0f / sum;
        const float* awr = aw + ((size_t)b*SEQ + q0 + r) * SEQ;
        float* ao = attn_out + ((size_t)bh*SEQ + q0 + r) * SEQ;
#pragma unroll
        for (int i = 0; i < 32; i++) {
            int k = lane + 32*i;
            float a = (Ss[r*SROW + k] * inv) * awr[k];
            Ss[r*SROW + k] = a;
            ao[k] = a;                      // coalesced attn output
        }
    }

    // -------- phase 2: X = A @ V --------
    float x00 = 0.f, x01 = 0.f, x10 = 0.f, x11 = 0.f;
    for (int vt = 0; vt < 8; vt++) {
        __syncthreads();
#pragma unroll
        for (int it = 0; it < 8; it++) {
            int lin = t + 256*it;
            int r = lin >> 4, c = (lin & 15) * 4;
            float4 v = *(const float4*)&Vg[(size_t)(vt*128 + r)*DEP + c];
            Ks[r*SD + c + 0] = v.x; Ks[r*SD + c + 1] = v.y;
            Ks[r*SD + c + 2] = v.z; Ks[r*SD + c + 3] = v.w;
        }
        __syncthreads();
#pragma unroll 8
        for (int kp = 0; kp < 128; kp++) {
            float a0 = Ss[qa*SROW + vt*128 + kp];    // broadcast
            float a1 = Ss[qb*SROW + vt*128 + kp];
            float v0 = Ks[kp*SD + lane];             // conflict-free
            float v1 = Ks[kp*SD + lane + 32];
            x00 = fmaf(a0, v0, x00); x01 = fmaf(a0, v1, x01);
            x10 = fmaf(a1, v0, x10); x11 = fmaf(a1, v1, x11);
        }
    }
    float* Xg = g_X + ((size_t)bh*SEQ + q0)*DEP;
    Xg[qa*DEP + lane]      = x00;
    Xg[qa*DEP + lane + 32] = x01;
    Xg[qb*DEP + lane]      = x10;
    Xg[qb*DEP + lane + 32] = x11;
}

// =========================================================================
extern "C" void kernel_launch(void* const* d_in, const int* in_sizes, int n_in,
                              void* d_out, int out_size)
{
    const float* q_in = (const float*)d_in[0];
    const float* k_in = (const float*)d_in[1];
    const float* v_in = (const float*)d_in[2];
    const float* mask = (const float*)d_in[3];
    const float* aw   = (const float*)d_in[4];
    const float* wq   = (const float*)d_in[5];
    const float* bq   = (const float*)d_in[6];
    const float* wk   = (const float*)d_in[7];
    const float* bk   = (const float*)d_in[8];
    const float* wv   = (const float*)d_in[9];
    const float* bv   = (const float*)d_in[10];
    const float* wo   = (const float*)d_in[11];
    const float* bo   = (const float*)d_in[12];

    float* out      = (float*)d_out;                       // [B,S,512]
    float* attn_out = out + (size_t)BB*SEQ*DM;             // [B,H,S,S] after out

    float *Qp, *Kp, *Vp;
    cudaGetSymbolAddress((void**)&Qp, g_Q);
    cudaGetSymbolAddress((void**)&Kp, g_K);
    cudaGetSymbolAddress((void**)&Vp, g_V);

    dim3 gproj(128, 8);
    proj_kernel<<<gproj, 256>>>(q_in, wq, bq, Qp);
    proj_kernel<<<gproj, 256>>>(k_in, wk, bk, Kp);
    proj_kernel<<<gproj, 256>>>(v_in, wv, bv, Vp);

    cudaFuncSetAttribute(attn_kernel,
                         cudaFuncAttributeMaxDynamicSharedMemorySize,
                         ATTN_SMEM_BYTES);
    attn_kernel<<<dim3(64, 8, 8), 256, ATTN_SMEM_BYTES>>>(mask, aw, attn_out);

    outproj_kernel<<<dim3(128, 8), 256>>>(wo, bo, out);
}

// round 7
// speedup vs baseline: 1.0010x; 1.0010x over previous
#include <cuda_runtime.h>
#include <math.h>

#define BB  8
#define HH  8
#define SEQ 1024
#define DM  512
#define DEP 64

// ---- scratch (allocation-free: device globals) --------------------------
__device__ float g_Q[BB*HH*SEQ*DEP];
__device__ float g_K[BB*HH*SEQ*DEP];
__device__ float g_V[BB*HH*SEQ*DEP];
__device__ float g_X[BB*HH*SEQ*DEP];

// ---- f32x2 packed helpers (sm_100+) -------------------------------------
__device__ __forceinline__ unsigned long long pk2(float lo, float hi) {
    unsigned long long r;
    asm("mov.b64 %0, {%1, %2};" : "=l"(r) : "f"(lo), "f"(hi));
    return r;
}
__device__ __forceinline__ void fma2(unsigned long long& d,
                                     unsigned long long a, unsigned long long b) {
    asm("fma.rn.f32x2 %0, %1, %2, %0;" : "+l"(d) : "l"(a), "l"(b));
}
__device__ __forceinline__ float2 upk(unsigned long long v) {
    float2 f;
    asm("mov.b64 {%0, %1}, %2;" : "=f"(f.x), "=f"(f.y) : "l"(v));
    return f;
}

// =========================================================================
// Projection GEMM: Out[b,h,s,d] = X[m,:] @ W[:,h*64+d] + bias
// BM=128 BN=64 BK=16, 128 threads, 8x8 microtile, f32x2 accumulators.
// =========================================================================
__global__ __launch_bounds__(128)
void proj_kernel(const float* __restrict__ X, const float* __restrict__ W,
                 const float* __restrict__ bias, float* __restrict__ Out)
{
    __shared__ float As[16*132];   // transposed: As[k][m]
    __shared__ float Bs[16*68];    // Bs[k][n]

    const int t  = threadIdx.x;
    const int tx = t & 7, ty = t >> 3;
    const int m0 = blockIdx.x * 128;
    const int h  = blockIdx.y;
    const int n0 = h * 64;

    unsigned long long acc[4][8];
#pragma unroll
    for (int i = 0; i < 4; i++)
#pragma unroll
        for (int c = 0; c < 8; c++) acc[i][c] = 0ull;

    for (int kk = 0; kk < DM; kk += 16) {
        // stage A transposed (thread t owns row m0+t)
#pragma unroll
        for (int j = 0; j < 4; j++) {
            float4 v = *(const float4*)&X[(size_t)(m0 + t)*DM + kk + 4*j];
            As[(4*j+0)*132 + t] = v.x;
            As[(4*j+1)*132 + t] = v.y;
            As[(4*j+2)*132 + t] = v.z;
            As[(4*j+3)*132 + t] = v.w;
        }
        // stage B
#pragma unroll
        for (int i = 0; i < 2; i++) {
            int idx = t + 128*i;
            int bk = idx >> 4, bc = (idx & 15)*4;
            *(float4*)&Bs[bk*68 + bc] =
                *(const float4*)&W[(size_t)(kk+bk)*DM + n0 + bc];
        }
        __syncthreads();
#pragma unroll
        for (int k = 0; k < 16; k++) {
            ulonglong2 apA = *(const ulonglong2*)&As[k*132 + ty*8];
            ulonglong2 apB = *(const ulonglong2*)&As[k*132 + ty*8 + 4];
            float4 blo = *(const float4*)&Bs[k*68 + tx*4];
            float4 bhi = *(const float4*)&Bs[k*68 + 32 + tx*4];
            float bf[8] = {blo.x, blo.y, blo.z, blo.w,
                           bhi.x, bhi.y, bhi.z, bhi.w};
#pragma unroll
            for (int c = 0; c < 8; c++) {
                unsigned long long bd = pk2(bf[c], bf[c]);
                fma2(acc[0][c], apA.x, bd);
                fma2(acc[1][c], apA.y, bd);
                fma2(acc[2][c], apB.x, bd);
                fma2(acc[3][c], apB.y, bd);
            }
        }
        __syncthreads();
    }

    float4 blo4 = *(const float4*)&bias[n0 + tx*4];
    float4 bhi4 = *(const float4*)&bias[n0 + 32 + tx*4];
#pragma unroll
    for (int rp = 0; rp < 4; rp++) {
        float ve[8], vo[8];
#pragma unroll
        for (int c = 0; c < 8; c++) {
            float2 f = upk(acc[rp][c]);
            ve[c] = f.x; vo[c] = f.y;
        }
#pragma unroll
        for (int e = 0; e < 2; e++) {
            const float* vv = e ? vo : ve;
            int m = m0 + ty*8 + 2*rp + e;
            int bbatch = m >> 10, s = m & 1023;
            float* dst = &Out[(((size_t)bbatch*HH + h)*SEQ + s)*DEP];
            *(float4*)&dst[tx*4] = make_float4(vv[0]+blo4.x, vv[1]+blo4.y,
                                               vv[2]+blo4.z, vv[3]+blo4.w);
            *(float4*)&dst[32+tx*4] = make_float4(vv[4]+bhi4.x, vv[5]+bhi4.y,
                                                  vv[6]+bhi4.z, vv[7]+bhi4.w);
        }
    }
}

// =========================================================================
// Output GEMM: out[m,n] = Xgather[m,:] @ wo + bo.  Same tiling.
// =========================================================================
__global__ __launch_bounds__(128)
void outproj_kernel(const float* __restrict__ W, const float* __restrict__ bias,
                    float* __restrict__ Out)
{
    __shared__ float As[16*132];
    __shared__ float Bs[16*68];

    const int t  = threadIdx.x;
    const int tx = t & 7, ty = t >> 3;
    const int m0 = blockIdx.x * 128;
    const int n0 = blockIdx.y * 64;

    unsigned long long acc[4][8];
#pragma unroll
    for (int i = 0; i < 4; i++)
#pragma unroll
        for (int c = 0; c < 8; c++) acc[i][c] = 0ull;

    const int mA = m0 + t;
    const int bbA = mA >> 10, sA = mA & 1023;

    for (int kk = 0; kk < DM; kk += 16) {
#pragma unroll
        for (int j = 0; j < 4; j++) {
            int kb = kk + 4*j;                   // stays within one head block
            int hsrc = kb >> 6, dd = kb & 63;
            float4 v = *(const float4*)
                &g_X[(((size_t)bbA*HH + hsrc)*SEQ + sA)*DEP + dd];
            As[(4*j+0)*132 + t] = v.x;
            As[(4*j+1)*132 + t] = v.y;
            As[(4*j+2)*132 + t] = v.z;
            As[(4*j+3)*132 + t] = v.w;
        }
#pragma unroll
        for (int i = 0; i < 2; i++) {
            int idx = t + 128*i;
            int bk = idx >> 4, bc = (idx & 15)*4;
            *(float4*)&Bs[bk*68 + bc] =
                *(const float4*)&W[(size_t)(kk+bk)*DM + n0 + bc];
        }
        __syncthreads();
#pragma unroll
        for (int k = 0; k < 16; k++) {
            ulonglong2 apA = *(const ulonglong2*)&As[k*132 + ty*8];
            ulonglong2 apB = *(const ulonglong2*)&As[k*132 + ty*8 + 4];
            float4 blo = *(const float4*)&Bs[k*68 + tx*4];
            float4 bhi = *(const float4*)&Bs[k*68 + 32 + tx*4];
            float bf[8] = {blo.x, blo.y, blo.z, blo.w,
                           bhi.x, bhi.y, bhi.z, bhi.w};
#pragma unroll
            for (int c = 0; c < 8; c++) {
                unsigned long long bd = pk2(bf[c], bf[c]);
                fma2(acc[0][c], apA.x, bd);
                fma2(acc[1][c], apA.y, bd);
                fma2(acc[2][c], apB.x, bd);
                fma2(acc[3][c], apB.y, bd);
            }
        }
        __syncthreads();
    }

    float4 blo4 = *(const float4*)&bias[n0 + tx*4];
    float4 bhi4 = *(const float4*)&bias[n0 + 32 + tx*4];
#pragma unroll
    for (int rp = 0; rp < 4; rp++) {
        float ve[8], vo[8];
#pragma unroll
        for (int c = 0; c < 8; c++) {
            float2 f = upk(acc[rp][c]);
            ve[c] = f.x; vo[c] = f.y;
        }
#pragma unroll
        for (int e = 0; e < 2; e++) {
            const float* vv = e ? vo : ve;
            int m = m0 + ty*8 + 2*rp + e;
            *(float4*)&Out[(size_t)m*DM + n0 + tx*4] =
                make_float4(vv[0]+blo4.x, vv[1]+blo4.y, vv[2]+blo4.z, vv[3]+blo4.w);
            *(float4*)&Out[(size_t)m*DM + n0 + 32 + tx*4] =
                make_float4(vv[4]+bhi4.x, vv[5]+bhi4.y, vv[6]+bhi4.z, vv[7]+bhi4.w);
        }
    }
}

// =========================================================================
// Attention.  One CTA per (b, h, 16-row q-tile).  256 threads, 8 warps.
// smem: Qpp (q-paired Q) | Ms | Ks (K/V tile 128x68) | Ss (16x1028 scores)
// Xpart reduction region overlaps Qpp+Ms (both dead by then).
// =========================================================================
#define KP   68                       // K/V tile pitch (floats)
#define SP   1028                     // score row pitch (floats)
#define OFF_QPP  0                    // 32*8 float4 = 1024 f
#define OFF_MS   (32*8*4)             // 1024 f
#define OFF_KS   (OFF_MS + SEQ)       // 128*KP f
#define OFF_SS   (OFF_KS + 128*KP)    // 16*SP f
#define ATTN_SMEM_BYTES ((OFF_SS + 16*SP) * 4)

__global__ __launch_bounds__(256, 2)
void attn_kernel(const float* __restrict__ mask, const float* __restrict__ aw,
                 float* __restrict__ attn_out)
{
    extern __shared__ float sm[];
    float*  Qpp = sm + OFF_QPP;   // float4 [32 d2][8 qp]
    float*  Ms  = sm + OFF_MS;
    float*  Ks  = sm + OFF_KS;
    float*  Ss  = sm + OFF_SS;

    const int t  = threadIdx.x;
    const int qt = blockIdx.x;
    const int h  = blockIdx.y;
    const int b  = blockIdx.z;
    const int bh = b*HH + h;
    const int q0 = qt*16;

    const float* Qg = g_Q + ((size_t)bh*SEQ + q0)*DEP;
    const float* Kg = g_K + (size_t)bh*SEQ*DEP;
    const float* Vg = g_V + (size_t)bh*SEQ*DEP;

    // ---- build q-paired Q layout + load mask ----------------------------
    {
        int d2 = t >> 3, qp = t & 7;
        float a0 = Qg[(2*qp  )*DEP + 2*d2    ];
        float a1 = Qg[(2*qp+1)*DEP + 2*d2    ];
        float b0 = Qg[(2*qp  )*DEP + 2*d2 + 1];
        float b1 = Qg[(2*qp+1)*DEP + 2*d2 + 1];
        *(float4*)&Qpp[(d2*8 + qp)*4] = make_float4(a0, a1, b0, b1);
    }
    for (int i = t; i < SEQ; i += 256) Ms[i] = mask[(size_t)b*SEQ + i];

    const int w = t >> 5, lane = t & 31;

    // ---- phase 1: scores (warp: qg = w&3 -> 4 q rows; sw = w>>2 k-half) --
    {
        const int qg  = w & 3;
        const int sw  = w >> 2;
        const int qp0 = qg*2, qp1 = qg*2 + 1;
        const int krow = sw*64 + lane;

        for (int kt = 0; kt < 8; kt++) {
            __syncthreads();
#pragma unroll
            for (int i = 0; i < 8; i++) {
                int lin = t + 256*i;
                int r = lin >> 4, c = (lin & 15)*4;
                *(float4*)&Ks[r*KP + c] =
                    *(const float4*)&Kg[(size_t)(kt*128 + r)*DEP + c];
            }
            __syncthreads();

            unsigned long long a00=0ull, a01=0ull, a10=0ull, a11=0ull;
#pragma unroll
            for (int ds = 0; ds < 16; ds++) {
                int d = ds*4;
                float4 ka = *(const float4*)&Ks[krow*KP + d];
                float4 kb = *(const float4*)&Ks[(krow+32)*KP + d];
                ulonglong2 qA = *(const ulonglong2*)&Qpp[((2*ds  )*8 + qp0)*4];
                ulonglong2 qB = *(const ulonglong2*)&Qpp[((2*ds  )*8 + qp1)*4];
                ulonglong2 qC = *(const ulonglong2*)&Qpp[((2*ds+1)*8 + qp0)*4];
                ulonglong2 qD = *(const ulonglong2*)&Qpp[((2*ds+1)*8 + qp1)*4];
                unsigned long long k0 = pk2(ka.x, ka.x), k1 = pk2(ka.y, ka.y);
                unsigned long long k2 = pk2(ka.z, ka.z), k3 = pk2(ka.w, ka.w);
                unsigned long long m0_ = pk2(kb.x, kb.x), m1_ = pk2(kb.y, kb.y);
                unsigned long long m2_ = pk2(kb.z, kb.z), m3_ = pk2(kb.w, kb.w);
                fma2(a00, k0, qA.x); fma2(a00, k1, qA.y);
                fma2(a00, k2, qC.x); fma2(a00, k3, qC.y);
                fma2(a01, m0_, qA.x); fma2(a01, m1_, qA.y);
                fma2(a01, m2_, qC.x); fma2(a01, m3_, qC.y);
                fma2(a10, k0, qB.x); fma2(a10, k1, qB.y);
                fma2(a10, k2, qD.x); fma2(a10, k3, qD.y);
                fma2(a11, m0_, qB.x); fma2(a11, m1_, qB.y);
                fma2(a11, m2_, qD.x); fma2(a11, m3_, qD.y);
            }
            int kk0 = kt*128 + krow;
            float2 f;
            f = upk(a00);
            Ss[(qg*4+0)*SP + kk0]      = f.x*0.125f;
            Ss[(qg*4+1)*SP + kk0]      = f.y*0.125f;
            f = upk(a01);
            Ss[(qg*4+0)*SP + kk0 + 32] = f.x*0.125f;
            Ss[(qg*4+1)*SP + kk0 + 32] = f.y*0.125f;
            f = upk(a10);
            Ss[(qg*4+2)*SP + kk0]      = f.x*0.125f;
            Ss[(qg*4+3)*SP + kk0]      = f.y*0.125f;
            f = upk(a11);
            Ss[(qg*4+2)*SP + kk0 + 32] = f.x*0.125f;
            Ss[(qg*4+3)*SP + kk0 + 32] = f.y*0.125f;
        }
    }
    __syncthreads();

    // ---- masked softmax + additional_weights (warp w: rows 2w, 2w+1) ----
#pragma unroll
    for (int rr = 0; rr < 2; rr++) {
        int r = 2*w + rr;
        float mx = -3.0e38f;
#pragma unroll
        for (int i = 0; i < 32; i++) {
            int k = lane + 32*i;
            float v = fmaf(Ms[k], -1.0e9f, Ss[r*SP + k]);
            Ss[r*SP + k] = v;
            mx = fmaxf(mx, v);
        }
#pragma unroll
        for (int off = 16; off > 0; off >>= 1)
            mx = fmaxf(mx, __shfl_xor_sync(0xffffffffu, mx, off));
        float sum = 0.f;
#pragma unroll
        for (int i = 0; i < 32; i++) {
            int k = lane + 32*i;
            float v = __expf(Ss[r*SP + k] - mx);
            Ss[r*SP + k] = v;
            sum += v;
        }
#pragma unroll
        for (int off = 16; off > 0; off >>= 1)
            sum += __shfl_xor_sync(0xffffffffu, sum, off);
        float inv = 1.0f / sum;
        const float* awr = aw + ((size_t)b*SEQ + q0 + r) * SEQ;
        float* ao = attn_out + ((size_t)bh*SEQ + q0 + r) * SEQ;
#pragma unroll
        for (int i = 0; i < 32; i++) {
            int k = lane + 32*i;
            float a = (Ss[r*SP + k] * inv) * awr[k];
            Ss[r*SP + k] = a;
            ao[k] = a;
        }
    }

    // ---- phase 2: X = A @ V  (warp: qg2 = w&3, half = w>>2 split-K) -----
    {
        const int qg2  = w & 3;
        const int half = w >> 2;
        const int qi   = lane >> 3;      // 0..3  -> q = qg2*4+qi
        const int dg   = lane & 7;       // d = 4dg..+3 and 32+4dg..+3
        unsigned long long xa0=0ull, xa1=0ull, xb0=0ull, xb1=0ull;

        for (int vt = 0; vt < 8; vt++) {
            __syncthreads();
#pragma unroll
            for (int i = 0; i < 8; i++) {
                int lin = t + 256*i;
                int r = lin >> 4, c = (lin & 15)*4;
                *(float4*)&Ks[r*KP + c] =
                    *(const float4*)&Vg[(size_t)(vt*128 + r)*DEP + c];
            }
            __syncthreads();

            const float* arow = &Ss[(qg2*4 + qi)*SP + vt*128 + half*64];
#pragma unroll
            for (int j4 = 0; j4 < 16; j4++) {
                float4 a4 = *(const float4*)&arow[j4*4];
                float av[4] = {a4.x, a4.y, a4.z, a4.w};
#pragma unroll
                for (int j = 0; j < 4; j++) {
                    unsigned long long ad = pk2(av[j], av[j]);
                    int vr = half*64 + j4*4 + j;
                    ulonglong2 v1 = *(const ulonglong2*)&Ks[vr*KP + 4*dg];
                    ulonglong2 v2 = *(const ulonglong2*)&Ks[vr*KP + 32 + 4*dg];
                    fma2(xa0, v1.x, ad); fma2(xa1, v1.y, ad);
                    fma2(xb0, v2.x, ad); fma2(xb1, v2.y, ad);
                }
            }
        }

        // partials -> smem (overlaps Qpp+Ms; both dead), reduce halves
        float* Xp = sm;                       // float [8][4][64]
        ulonglong2 pa; pa.x = xa0; pa.y = xa1;
        ulonglong2 pb; pb.x = xb0; pb.y = xb1;
        *(ulonglong2*)&Xp[w*256 + qi*64 + 4*dg]      = pa;
        *(ulonglong2*)&Xp[w*256 + qi*64 + 32 + 4*dg] = pb;
    }
    __syncthreads();
    {
        float* Xp = sm;
        int q = t >> 4, c4 = (t & 15) * 4;
        int base = (q >> 2)*256 + (q & 3)*64 + c4;
        float4 u = *(float4*)&Xp[base];
        float4 v = *(float4*)&Xp[base + 4*256];
        *(float4*)&g_X[((size_t)bh*SEQ + q0 + q)*DEP + c4] =
            make_float4(u.x+v.x, u.y+v.y, u.z+v.z, u.w+v.w);
    }
}

// =========================================================================
extern "C" void kernel_launch(void* const* d_in, const int* in_sizes, int n_in,
                              void* d_out, int out_size)
{
    const float* q_in = (const float*)d_in[0];
    const float* k_in = (const float*)d_in[1];
    const float* v_in = (const float*)d_in[2];
    const float* mask = (const float*)d_in[3];
    const float* aw   = (const float*)d_in[4];
    const float* wq   = (const float*)d_in[5];
    const float* bq   = (const float*)d_in[6];
    const float* wk   = (const float*)d_in[7];
    const float* bk   = (const float*)d_in[8];
    const float* wv   = (const float*)d_in[9];
    const float* bv   = (const float*)d_in[10];
    const float* wo   = (const float*)d_in[11];
    const float* bo   = (const float*)d_in[12];

    float* out      = (float*)d_out;                // [B,S,512]
    float* attn_out = out + (size_t)BB*SEQ*DM;      // [B,H,S,S]

    float *Qp, *Kp, *Vp;
    cudaGetSymbolAddress((void**)&Qp, g_Q);
    cudaGetSymbolAddress((void**)&Kp, g_K);
    cudaGetSymbolAddress((void**)&Vp, g_V);

    dim3 gproj(64, 8);
    proj_kernel<<<gproj, 128>>>(q_in, wq, bq, Qp);
    proj_kernel<<<gproj, 128>>>(k_in, wk, bk, Kp);
    proj_kernel<<<gproj, 128>>>(v_in, wv, bv, Vp);

    cudaFuncSetAttribute(attn_kernel,
                         cudaFuncAttributeMaxDynamicSharedMemorySize,
                         ATTN_SMEM_BYTES);
    attn_kernel<<<dim3(64, 8, 8), 256, ATTN_SMEM_BYTES>>>(mask, aw, attn_out);

    outproj_kernel<<<dim3(64, 8), 128>>>(wo, bo, out);
}